// round 15
// baseline (speedup 1.0000x reference)
#include <cuda_runtime.h>
#include <cuda_bf16.h>
#include <cstdint>

#define NN 4096
#define CC 96
#define EE 131072
#define NHEADS 4
#define DH 24
#define SPLITS 16

typedef unsigned long long u64;

// ---------------- scratch ----------------
__device__ float g_h[NN*CC];
__device__ float g_agg[NN*CC];
__device__ float g_t1[NN*CC];
__device__ float g_pre1[NN*CC];
__device__ float g_qkv[NN*3*CC];
__device__ float g_attno[NN*CC];
__device__ float g_pre2[NN*CC];
__device__ float g_outb[NN*CC];
__device__ float g_t2[NN*2*CC];
__device__ float g_pre3[NN*CC];
__device__ float g_y[NN*CC];
__device__ float g_stats[12*CC];
__device__ int   g_src[EE];
__device__ int   g_dst[EE];
__device__ int   g_eat[EE];
__device__ int   g_flags[2];
__device__ int   g_cnt[NN];
__device__ int   g_off[NN+1];
__device__ int   g_cur[NN];
__device__ int   g_csrc[EE];
__device__ int   g_ceat[EE];
__device__ float g_po[SPLITS*NHEADS*NN*DH];
__device__ float g_pl[SPLITS*NHEADS*NN];
// packed attention operands: [h*24+d][key]
__device__ unsigned       g_kt[NHEADS*DH*NN];
__device__ unsigned short g_vh[NHEADS*DH*NN];

// ---------------- mma.sync helpers ----------------
__device__ __forceinline__ unsigned f2tf32(float f) {
    unsigned r; asm("cvt.rna.tf32.f32 %0, %1;" : "=r"(r) : "f"(f)); return r;
}
__device__ __forceinline__ unsigned pkbf(float lo, float hi) {
    unsigned r; asm("cvt.rn.bf16x2.f32 %0, %1, %2;" : "=r"(r) : "f"(hi), "f"(lo)); return r;
}
__device__ __forceinline__ void mma_tf32(float* c, const unsigned* a, const unsigned* b) {
    asm volatile("mma.sync.aligned.m16n8k8.row.col.f32.tf32.tf32.f32 "
        "{%0,%1,%2,%3}, {%4,%5,%6,%7}, {%8,%9}, {%0,%1,%2,%3};"
        : "+f"(c[0]), "+f"(c[1]), "+f"(c[2]), "+f"(c[3])
        : "r"(a[0]), "r"(a[1]), "r"(a[2]), "r"(a[3]), "r"(b[0]), "r"(b[1]));
}
__device__ __forceinline__ void mma_bf16(float* c, const unsigned* a, const unsigned* b) {
    asm volatile("mma.sync.aligned.m16n8k16.row.col.f32.bf16.bf16.f32 "
        "{%0,%1,%2,%3}, {%4,%5,%6,%7}, {%8,%9}, {%0,%1,%2,%3};"
        : "+f"(c[0]), "+f"(c[1]), "+f"(c[2]), "+f"(c[3])
        : "r"(a[0]), "r"(a[1]), "r"(a[2]), "r"(a[3]), "r"(b[0]), "r"(b[1]));
}
__device__ __forceinline__ void cp16(unsigned dst_smem, const void* src) {
    asm volatile("cp.async.cg.shared.global [%0], [%1], 16;" :: "r"(dst_smem), "l"(src));
}

// ---------------- prologue ----------------
__global__ void prep(const unsigned* __restrict__ ei, const unsigned* __restrict__ ea) {
    int t = blockIdx.x * blockDim.x + threadIdx.x;
    if (blockIdx.x == 0 && threadIdx.x < 32) {
        int lane = threadIdx.x;
        unsigned v1 = (lane < 16) ? ei[2 * lane + 1] : 0u;
        unsigned v2 = (lane < 16) ? ea[2 * lane + 1] : 0u;
        unsigned b1 = __ballot_sync(0xffffffffu, v1 != 0u);
        unsigned b2 = __ballot_sync(0xffffffffu, v2 != 0u);
        if (lane == 0) { g_flags[0] = (b1 == 0u); g_flags[1] = (b2 == 0u); }
    }
    if (t < NN) g_cnt[t] = 0;
    if (t < 12 * CC) g_stats[t] = 0.f;
}

__global__ void decode_idx(const void* __restrict__ ei, const void* __restrict__ ea) {
    int e = blockIdx.x * blockDim.x + threadIdx.x;
    if (e >= EE) return;
    int s, d, a;
    if (g_flags[0]) {
        const long long* p = (const long long*)ei;
        s = (int)p[e]; d = (int)p[EE + e];
    } else {
        const int* p = (const int*)ei;
        s = p[e]; d = p[EE + e];
    }
    if (g_flags[1]) {
        const long long* p = (const long long*)ea;
        a = (int)p[e];
    } else {
        const int* p = (const int*)ea;
        a = p[e];
    }
    g_src[e] = s; g_dst[e] = d; g_eat[e] = a;
    atomicAdd(&g_cnt[d], 1);
}

// shfl-based two-level scan (1024 threads, 4 elems/thread)
__global__ __launch_bounds__(1024) void csr_scan() {
    __shared__ int wsum[32];
    int t = threadIdx.x;
    int lane = t & 31, wid = t >> 5;
    int c0 = g_cnt[4*t], c1 = g_cnt[4*t+1], c2 = g_cnt[4*t+2], c3 = g_cnt[4*t+3];
    int s = c0 + c1 + c2 + c3;
    int v = s;
    #pragma unroll
    for (int o = 1; o < 32; o <<= 1) {
        int n = __shfl_up_sync(0xffffffffu, v, o);
        if (lane >= o) v += n;
    }
    if (lane == 31) wsum[wid] = v;
    __syncthreads();
    if (wid == 0) {
        int x = wsum[lane];
        #pragma unroll
        for (int o = 1; o < 32; o <<= 1) {
            int n = __shfl_up_sync(0xffffffffu, x, o);
            if (lane >= o) x += n;
        }
        wsum[lane] = x;
    }
    __syncthreads();
    int incl = v + (wid ? wsum[wid - 1] : 0);
    int base = incl - s;
    g_off[4*t] = base;            g_cur[4*t] = base;
    g_off[4*t+1] = base+c0;       g_cur[4*t+1] = base+c0;
    g_off[4*t+2] = base+c0+c1;    g_cur[4*t+2] = base+c0+c1;
    g_off[4*t+3] = base+c0+c1+c2; g_cur[4*t+3] = base+c0+c1+c2;
    if (t == 1023) g_off[NN] = incl;
}
__global__ void csr_fill() {
    int e = blockIdx.x * blockDim.x + threadIdx.x;
    if (e >= EE) return;
    int pos = atomicAdd(&g_cur[g_dst[e]], 1);
    g_csrc[pos] = g_src[e];
    g_ceat[pos] = g_eat[e];
}

// ---------------- GINE aggregate ----------------
__global__ __launch_bounds__(256) void gine_agg(const float* __restrict__ h,
                                                const float* __restrict__ emb,
                                                float* __restrict__ agg) {
    int warp = (blockIdx.x * 256 + threadIdx.x) >> 5;
    int lane = threadIdx.x & 31;
    if (warp >= NN) return;
    int beg = g_off[warp], end = g_off[warp + 1];
    float a0 = 0.f, a1 = 0.f, a2 = 0.f;
    for (int i = beg; i < end; i++) {
        int src = g_csrc[i], et = g_ceat[i];
        const float* hp = h + (size_t)src * CC;
        const float* ep = emb + (size_t)et * CC;
        a0 += fmaxf(hp[lane]      + ep[lane],      0.f);
        a1 += fmaxf(hp[lane + 32] + ep[lane + 32], 0.f);
        a2 += fmaxf(hp[lane + 64] + ep[lane + 64], 0.f);
    }
    float* ap = agg + (size_t)warp * CC;
    ap[lane] = a0; ap[lane + 32] = a1; ap[lane + 64] = a2;
}

// ---------------- 3xTF32 tensor-core GEMM with fused epilogue ----------------
__global__ __launch_bounds__(128) void tgemm(
    const float* __restrict__ A, const float* __restrict__ A2,
    const float* __restrict__ W, const float* __restrict__ bias,
    const float* __restrict__ res, float* __restrict__ C,
    int M, int N, int K, int relu,
    float* __restrict__ st_s, float* __restrict__ st_s2,
    unsigned* __restrict__ kt_out, unsigned short* __restrict__ vh_out)
{
    __shared__ __align__(16) unsigned Bhi[32 * 40];
    __shared__ __align__(16) unsigned Blo[32 * 40];
    __shared__ float Ssum[4][32];
    __shared__ float Ssq[4][32];
    const int tid = threadIdx.x;
    const int w = tid >> 5, lane = tid & 31;
    const int tg = lane >> 2, tq = lane & 3;
    const int row0 = blockIdx.y * 64 + w * 16;
    const int col0 = blockIdx.x * 32;

    float c[4][4];
    #pragma unroll
    for (int nt = 0; nt < 4; nt++)
        #pragma unroll
        for (int r = 0; r < 4; r++) c[nt][r] = 0.f;

    for (int k0 = 0; k0 < K; k0 += 32) {
        __syncthreads();
        #pragma unroll
        for (int j = 0; j < 2; j++) {
            int idx = tid + j * 128;
            int r = idx >> 3, c4 = (idx & 7) * 4;
            float4 v = *(const float4*)(W + (size_t)(k0 + r) * N + col0 + c4);
            unsigned h0 = f2tf32(v.x), h1 = f2tf32(v.y), h2 = f2tf32(v.z), h3 = f2tf32(v.w);
            *(uint4*)&Bhi[r * 40 + c4] = make_uint4(h0, h1, h2, h3);
            *(uint4*)&Blo[r * 40 + c4] = make_uint4(
                f2tf32(v.x - __uint_as_float(h0)), f2tf32(v.y - __uint_as_float(h1)),
                f2tf32(v.z - __uint_as_float(h2)), f2tf32(v.w - __uint_as_float(h3)));
        }
        __syncthreads();
        #pragma unroll
        for (int kc = 0; kc < 4; kc++) {
            const float* ap0 = A + (size_t)(row0 + tg) * K + k0 + kc * 8;
            const float* ap1 = A + (size_t)(row0 + tg + 8) * K + k0 + kc * 8;
            float av[4];
            av[0] = ap0[tq]; av[1] = ap1[tq]; av[2] = ap0[tq + 4]; av[3] = ap1[tq + 4];
            if (A2) {
                const float* bp0 = A2 + (size_t)(row0 + tg) * K + k0 + kc * 8;
                const float* bp1 = A2 + (size_t)(row0 + tg + 8) * K + k0 + kc * 8;
                av[0] += bp0[tq]; av[1] += bp1[tq]; av[2] += bp0[tq + 4]; av[3] += bp1[tq + 4];
            }
            unsigned ahi[4], alo[4];
            #pragma unroll
            for (int r = 0; r < 4; r++) {
                ahi[r] = f2tf32(av[r]);
                alo[r] = f2tf32(av[r] - __uint_as_float(ahi[r]));
            }
            const int kr0 = (kc * 8 + tq) * 40;
            const int kr1 = (kc * 8 + tq + 4) * 40;
            #pragma unroll
            for (int nt = 0; nt < 4; nt++) {
                unsigned bh[2], bl[2];
                bh[0] = Bhi[kr0 + nt * 8 + tg]; bh[1] = Bhi[kr1 + nt * 8 + tg];
                bl[0] = Blo[kr0 + nt * 8 + tg]; bl[1] = Blo[kr1 + nt * 8 + tg];
                mma_tf32(c[nt], ahi, bh);
                mma_tf32(c[nt], ahi, bl);
                mma_tf32(c[nt], alo, bh);
            }
        }
    }

    float myS[8], myQ[8];
    #pragma unroll
    for (int nt = 0; nt < 4; nt++) {
        int cc0 = col0 + nt * 8 + 2 * tq;
        float b0 = bias[cc0], b1 = bias[cc0 + 1];
        float v00 = c[nt][0] + b0, v01 = c[nt][1] + b1;
        float v10 = c[nt][2] + b0, v11 = c[nt][3] + b1;
        if (res) {
            float2 r0v = *(const float2*)(res + (size_t)(row0 + tg) * N + cc0);
            float2 r1v = *(const float2*)(res + (size_t)(row0 + tg + 8) * N + cc0);
            v00 += r0v.x; v01 += r0v.y; v10 += r1v.x; v11 += r1v.y;
        }
        if (relu) {
            v00 = fmaxf(v00, 0.f); v01 = fmaxf(v01, 0.f);
            v10 = fmaxf(v10, 0.f); v11 = fmaxf(v11, 0.f);
        }
        *(float2*)(C + (size_t)(row0 + tg) * N + cc0) = make_float2(v00, v01);
        *(float2*)(C + (size_t)(row0 + tg + 8) * N + cc0) = make_float2(v10, v11);

        if (kt_out && cc0 >= CC) {
            #pragma unroll
            for (int jj = 0; jj < 2; jj++) {
                int col = cc0 + jj;
                float va = jj ? v01 : v00;
                float vb = jj ? v11 : v10;
                if (col < 2 * CC) {
                    kt_out[(size_t)(col - CC) * NN + row0 + tg] = f2tf32(va);
                    kt_out[(size_t)(col - CC) * NN + row0 + tg + 8] = f2tf32(vb);
                } else {
                    vh_out[(size_t)(col - 2 * CC) * NN + row0 + tg] =
                        __bfloat16_as_ushort(__float2bfloat16(va));
                    vh_out[(size_t)(col - 2 * CC) * NN + row0 + tg + 8] =
                        __bfloat16_as_ushort(__float2bfloat16(vb));
                }
            }
        }

        myS[nt * 2] = v00 + v10;           myS[nt * 2 + 1] = v01 + v11;
        myQ[nt * 2] = v00 * v00 + v10 * v10; myQ[nt * 2 + 1] = v01 * v01 + v11 * v11;
    }

    if (st_s) {
        #pragma unroll
        for (int i = 0; i < 8; i++) {
            #pragma unroll
            for (int o = 4; o <= 16; o <<= 1) {
                myS[i] += __shfl_xor_sync(0xffffffffu, myS[i], o);
                myQ[i] += __shfl_xor_sync(0xffffffffu, myQ[i], o);
            }
        }
        if (tg == 0) {
            #pragma unroll
            for (int nt = 0; nt < 4; nt++) {
                Ssum[w][nt * 8 + 2 * tq] = myS[nt * 2];
                Ssum[w][nt * 8 + 2 * tq + 1] = myS[nt * 2 + 1];
                Ssq[w][nt * 8 + 2 * tq] = myQ[nt * 2];
                Ssq[w][nt * 8 + 2 * tq + 1] = myQ[nt * 2 + 1];
            }
        }
        __syncthreads();
        if (tid < 32) {
            float a = Ssum[0][tid] + Ssum[1][tid] + Ssum[2][tid] + Ssum[3][tid];
            float b = Ssq[0][tid] + Ssq[1][tid] + Ssq[2][tid] + Ssq[3][tid];
            atomicAdd(&st_s[col0 + tid], a);
            atomicAdd(&st_s2[col0 + tid], b);
        }
    }
}

// ---------------- mma.sync flash attention (cp.async double-buffered, half-tiles) ----------------
#define QSCALE 0.2944858445807166f
#define NTILES ((NN / SPLITS) / 64)

__global__ __launch_bounds__(128) void flash_mma(const float* __restrict__ qkv,
                                                 const unsigned* __restrict__ kt,
                                                 const unsigned short* __restrict__ vh,
                                                 float* __restrict__ po,
                                                 float* __restrict__ pl) {
    __shared__ __align__(16) unsigned KtU[2][24 * 72];
    __shared__ __align__(16) unsigned short Vh[2][24 * 72];
    const int h   = blockIdx.y;
    const int q0  = blockIdx.x * 128;
    const int sp  = blockIdx.z;
    const int tid = threadIdx.x;
    const int w   = tid >> 5;
    const int lane = tid & 31;
    const int tg = lane >> 2, tq = lane & 3;

    const unsigned* ktb0 = kt + (size_t)h * DH * NN + sp * (NN / SPLITS);
    const unsigned short* vhb0 = vh + (size_t)h * DH * NN + sp * (NN / SPLITS);

    auto stage = [&](int t, int buf) {
        const unsigned* ktb = ktb0 + t * 64;
        const unsigned short* vhb = vhb0 + t * 64;
        unsigned kbase = (unsigned)__cvta_generic_to_shared(&KtU[buf][0]);
        unsigned vbase = (unsigned)__cvta_generic_to_shared(&Vh[buf][0]);
        #pragma unroll
        for (int ii = 0; ii < 3; ii++) {              // K ops 0..383
            int idx = tid + ii * 128;
            int row = idx >> 4, q = idx & 15;
            cp16(kbase + (row * 72 + q * 4) * 4, ktb + (size_t)row * NN + q * 4);
        }
        {                                             // V ops 0..127
            int row = tid >> 3, q = tid & 7;
            cp16(vbase + (row * 72 + q * 8) * 2, vhb + (size_t)row * NN + q * 8);
        }
        if (tid < 64) {                               // V ops 128..191
            int idx = 128 + tid;
            int row = idx >> 3, q = idx & 7;
            cp16(vbase + (row * 72 + q * 8) * 2, vhb + (size_t)row * NN + q * 8);
        }
        asm volatile("cp.async.commit_group;" ::: "memory");
    };

    unsigned QA[2][3][4];
    #pragma unroll
    for (int mi = 0; mi < 2; mi++) {
        const float* qp0 = qkv + (size_t)(q0 + 32 * w + 16 * mi + tg) * (3 * CC) + h * DH;
        const float* qp1 = qp0 + (size_t)8 * (3 * CC);
        #pragma unroll
        for (int kc = 0; kc < 3; kc++) {
            QA[mi][kc][0] = f2tf32(qp0[kc * 8 + tq] * QSCALE);
            QA[mi][kc][1] = f2tf32(qp1[kc * 8 + tq] * QSCALE);
            QA[mi][kc][2] = f2tf32(qp0[kc * 8 + tq + 4] * QSCALE);
            QA[mi][kc][3] = f2tf32(qp1[kc * 8 + tq + 4] * QSCALE);
        }
    }

    float OC[2][3][4];
    #pragma unroll
    for (int mi = 0; mi < 2; mi++)
        #pragma unroll
        for (int n = 0; n < 3; n++)
            #pragma unroll
            for (int r = 0; r < 4; r++) OC[mi][n][r] = 0.f;
    float lacc[2][2] = {{0.f, 0.f}, {0.f, 0.f}};

    stage(0, 0);

    for (int t = 0; t < NTILES; t++) {
        const int buf = t & 1;
        if (t + 1 < NTILES) {
            stage(t + 1, buf ^ 1);
            asm volatile("cp.async.wait_group 1;" ::: "memory");
        } else {
            asm volatile("cp.async.wait_group 0;" ::: "memory");
        }
        __syncthreads();

        #pragma unroll
        for (int kh = 0; kh < 2; kh++) {            // two 32-key halves
            float SC[2][4][4];
            #pragma unroll
            for (int mi = 0; mi < 2; mi++)
                #pragma unroll
                for (int nt = 0; nt < 4; nt++)
                    #pragma unroll
                    for (int r = 0; r < 4; r++) SC[mi][nt][r] = 0.f;

            #pragma unroll
            for (int nt = 0; nt < 4; nt++) {
                const int nc = kh * 32 + nt * 8 + tg;
                unsigned bB[3][2];
                #pragma unroll
                for (int kc = 0; kc < 3; kc++) {
                    bB[kc][0] = KtU[buf][(kc * 8 + tq) * 72 + nc];
                    bB[kc][1] = KtU[buf][(kc * 8 + tq + 4) * 72 + nc];
                }
                #pragma unroll
                for (int kc = 0; kc < 3; kc++) {
                    mma_tf32(SC[0][nt], QA[0][kc], bB[kc]);
                    mma_tf32(SC[1][nt], QA[1][kc], bB[kc]);
                }
            }

            #pragma unroll
            for (int mi = 0; mi < 2; mi++)
                #pragma unroll
                for (int nt = 0; nt < 4; nt++)
                    #pragma unroll
                    for (int r = 0; r < 4; r++) {
                        float e;
                        asm("ex2.approx.ftz.f32 %0, %1;" : "=f"(e) : "f"(SC[mi][nt][r]));
                        SC[mi][nt][r] = e;
                        lacc[mi][r >> 1] += e;
                    }

            unsigned PA[2][2][4];
            #pragma unroll
            for (int mi = 0; mi < 2; mi++)
                #pragma unroll
                for (int kc4 = 0; kc4 < 2; kc4++) {
                    PA[mi][kc4][0] = pkbf(SC[mi][2 * kc4][0],     SC[mi][2 * kc4][1]);
                    PA[mi][kc4][1] = pkbf(SC[mi][2 * kc4][2],     SC[mi][2 * kc4][3]);
                    PA[mi][kc4][2] = pkbf(SC[mi][2 * kc4 + 1][0], SC[mi][2 * kc4 + 1][1]);
                    PA[mi][kc4][3] = pkbf(SC[mi][2 * kc4 + 1][2], SC[mi][2 * kc4 + 1][3]);
                }

            #pragma unroll
            for (int kc4 = 0; kc4 < 2; kc4++) {
                #pragma unroll
                for (int n = 0; n < 3; n++) {
                    int drow = n * 8 + tg;
                    int col = kh * 32 + kc4 * 16 + 2 * tq;
                    unsigned bh[2];
                    bh[0] = *(const unsigned*)&Vh[buf][drow * 72 + col];
                    bh[1] = *(const unsigned*)&Vh[buf][drow * 72 + col + 8];
                    mma_bf16(OC[0][n], PA[0][kc4], bh);
                    mma_bf16(OC[1][n], PA[1][kc4], bh);
                }
            }
        }
        __syncthreads();
    }

    #pragma unroll
    for (int mi = 0; mi < 2; mi++)
        #pragma unroll
        for (int hi = 0; hi < 2; hi++) {
            float v = lacc[mi][hi];
            v += __shfl_xor_sync(0xffffffffu, v, 1);
            v += __shfl_xor_sync(0xffffffffu, v, 2);
            lacc[mi][hi] = v;
        }

    const int base = (sp * NHEADS + h) * NN;
    #pragma unroll
    for (int mi = 0; mi < 2; mi++) {
        int r0 = q0 + 32 * w + 16 * mi + tg;
        int r1 = r0 + 8;
        if (tq == 0) {
            pl[base + r0] = lacc[mi][0];
            pl[base + r1] = lacc[mi][1];
        }
        #pragma unroll
        for (int n = 0; n < 3; n++) {
            float2 v0 = make_float2(OC[mi][n][0], OC[mi][n][1]);
            float2 v1 = make_float2(OC[mi][n][2], OC[mi][n][3]);
            *(float2*)(po + ((size_t)(base + r0)) * DH + n * 8 + 2 * tq) = v0;
            *(float2*)(po + ((size_t)(base + r1)) * DH + n * 8 + 2 * tq) = v1;
        }
    }
}

__global__ void flash_combine(const float* __restrict__ po, const float* __restrict__ pl,
                              float* __restrict__ outp) {
    int t = blockIdx.x * blockDim.x + threadIdx.x;
    if (t >= NN * NHEADS) return;
    int q = t & (NN - 1);
    int h = t >> 12;
    float L = 0.f;
    #pragma unroll
    for (int s = 0; s < SPLITS; s++) L += pl[(s * NHEADS + h) * NN + q];
    float inv = 1.f / L;
    float* op = outp + (size_t)q * CC + h * DH;
    #pragma unroll
    for (int d = 0; d < DH; d += 4) {
        float4 acc = make_float4(0.f, 0.f, 0.f, 0.f);
        #pragma unroll
        for (int s = 0; s < SPLITS; s++) {
            const float4 v = *(const float4*)(po + ((size_t)(s * NHEADS + h) * NN + q) * DH + d);
            acc.x += v.x; acc.y += v.y; acc.z += v.z; acc.w += v.w;
        }
        acc.x *= inv; acc.y *= inv; acc.z *= inv; acc.w *= inv;
        *(float4*)(op + d) = acc;
    }
}

// ---------------- BN elementwise ----------------
__global__ void bn2_add(const float* __restrict__ p1, const float* __restrict__ p2,
                        const float* __restrict__ st,
                        const float* __restrict__ g1, const float* __restrict__ b1,
                        const float* __restrict__ g2, const float* __restrict__ b2,
                        float* __restrict__ out) {
    int i = blockIdx.x * blockDim.x + threadIdx.x;
    if (i >= NN * CC) return;
    int c = i % CC;
    const float invn = 1.f / NN;
    float m1 = st[c] * invn;
    float v1 = st[CC + c] * invn - m1 * m1;
    float m2 = st[2 * CC + c] * invn;
    float v2 = st[3 * CC + c] * invn - m2 * m2;
    float o = (p1[i] - m1) * rsqrtf(v1 + 1e-5f) * g1[c] + b1[c]
            + (p2[i] - m2) * rsqrtf(v2 + 1e-5f) * g2[c] + b2[c];
    out[i] = o;
}

__global__ void bn_apply(const float* __restrict__ p, const float* __restrict__ s,
                         const float* __restrict__ s2, const float* __restrict__ g,
                         const float* __restrict__ b, float* __restrict__ o) {
    int i = blockIdx.x * blockDim.x + threadIdx.x;
    if (i >= NN * CC) return;
    int c = i % CC;
    const float invn = 1.f / NN;
    float m = s[c] * invn;
    float v = s2[c] * invn - m * m;
    o[i] = (p[i] - m) * rsqrtf(v + 1e-5f) * g[c] + b[c];
}

// ---------------- final per-row LayerNorm ----------------
__global__ void out_ln(const float* __restrict__ y, const float* __restrict__ g,
                       const float* __restrict__ b, float* __restrict__ out) {
    int lane = threadIdx.x & 31;
    int warp = threadIdx.x >> 5;
    int row  = blockIdx.x * 4 + warp;
    const float* yr = y + (size_t)row * CC;
    float v0 = yr[lane], v1 = yr[lane + 32], v2 = yr[lane + 64];
    float s = v0 + v1 + v2;
    #pragma unroll
    for (int o = 16; o; o >>= 1) s += __shfl_xor_sync(0xffffffffu, s, o);
    float mean = s * (1.f / 96.f);
    float d0 = v0 - mean, d1 = v1 - mean, d2 = v2 - mean;
    float qv = d0 * d0 + d1 * d1 + d2 * d2;
    #pragma unroll
    for (int o = 16; o; o >>= 1) qv += __shfl_xor_sync(0xffffffffu, qv, o);
    float inv = rsqrtf(qv * (1.f / 96.f) + 1e-5f);
    float* orow = out + (size_t)row * CC;
    orow[lane]      = d0 * inv * g[lane]      + b[lane];
    orow[lane + 32] = d1 * inv * g[lane + 32] + b[lane + 32];
    orow[lane + 64] = d2 * inv * g[lane + 64] + b[lane + 64];
}

// ---------------- launch ----------------
extern "C" void kernel_launch(void* const* d_in, const int* in_sizes, int n_in,
                              void* d_out, int out_size) {
    const float*     x    = (const float*)d_in[0];
    const void*      ei   = d_in[1];
    const void*      ea   = d_in[2];
    const float*     w_in = (const float*)d_in[3];
    const float*     b_in = (const float*)d_in[4];
    const float*     emb  = (const float*)d_in[5];
    const float*     gw1  = (const float*)d_in[6];
    const float*     gb1  = (const float*)d_in[7];
    const float*     gw2  = (const float*)d_in[8];
    const float*     gb2  = (const float*)d_in[9];
    const float*     wqkv = (const float*)d_in[10];
    const float*     bqkv = (const float*)d_in[11];
    const float*     wo   = (const float*)d_in[12];
    const float*     bo   = (const float*)d_in[13];
    const float*     bng  = (const float*)d_in[14];
    const float*     bnb  = (const float*)d_in[15];
    const float*     fw1  = (const float*)d_in[16];
    const float*     fb1  = (const float*)d_in[17];
    const float*     fw2  = (const float*)d_in[18];
    const float*     fb2  = (const float*)d_in[19];
    const float*     w_o  = (const float*)d_in[20];
    const float*     b_o  = (const float*)d_in[21];
    const float*     lng  = (const float*)d_in[22];
    const float*     lnb  = (const float*)d_in[23];
    float* out = (float*)d_out;

    float *h_, *agg_, *t1_, *pre1_, *qkv_, *attno_, *pre2_, *outb_, *t2_, *pre3_, *y_, *stA_;
    float *po_, *pl_;
    unsigned* kt_;
    unsigned short* vh_;
    cudaGetSymbolAddress((void**)&h_,    g_h);
    cudaGetSymbolAddress((void**)&agg_,  g_agg);
    cudaGetSymbolAddress((void**)&t1_,   g_t1);
    cudaGetSymbolAddress((void**)&pre1_, g_pre1);
    cudaGetSymbolAddress((void**)&qkv_,  g_qkv);
    cudaGetSymbolAddress((void**)&attno_,g_attno);
    cudaGetSymbolAddress((void**)&pre2_, g_pre2);
    cudaGetSymbolAddress((void**)&outb_, g_outb);
    cudaGetSymbolAddress((void**)&t2_,   g_t2);
    cudaGetSymbolAddress((void**)&pre3_, g_pre3);
    cudaGetSymbolAddress((void**)&y_,    g_y);
    cudaGetSymbolAddress((void**)&stA_,  g_stats);
    cudaGetSymbolAddress((void**)&po_,   g_po);
    cudaGetSymbolAddress((void**)&pl_,   g_pl);
    cudaGetSymbolAddress((void**)&kt_,   g_kt);
    cudaGetSymbolAddress((void**)&vh_,   g_vh);

    cudaStream_t s1;
    cudaStreamCreateWithFlags(&s1, cudaStreamNonBlocking);
    cudaEvent_t evF[2], evJ[2];
    for (int i = 0; i < 2; i++) {
        cudaEventCreateWithFlags(&evF[i], cudaEventDisableTiming);
        cudaEventCreateWithFlags(&evJ[i], cudaEventDisableTiming);
    }

    auto gemm = [&](const float* A, const float* A2, const float* W, const float* bias,
                    const float* res, float* Cp, int M, int Nc, int K, int relu,
                    float* ss, float* ss2, cudaStream_t st,
                    unsigned* kto = nullptr, unsigned short* vho = nullptr) {
        dim3 grid(Nc / 32, M / 64);
        tgemm<<<grid, 128, 0, st>>>(A, A2, W, bias, res, Cp, M, Nc, K, relu, ss, ss2, kto, vho);
    };

    const int NCEL = NN * CC;

    prep<<<16, 256>>>((const unsigned*)ei, (const unsigned*)ea);
    gemm(x, nullptr, w_in, b_in, nullptr, h_, NN, CC, 64, 0, nullptr, nullptr, 0);

    for (int i = 0; i < 2; i++) {
        float* st_ = stA_ + (size_t)i * 6 * CC;

        cudaEventRecord(evF[i], 0);

        // --- main stream: attention branch ---
        gemm(h_, nullptr, wqkv + (size_t)i * CC * 3 * CC, bqkv + (size_t)i * 3 * CC,
             nullptr, qkv_, NN, 3 * CC, CC, 0, nullptr, nullptr, 0, kt_, vh_);
        flash_mma<<<dim3(NN / 128, NHEADS, SPLITS), 128>>>(qkv_, kt_, vh_, po_, pl_);
        flash_combine<<<(NN * NHEADS + 255) / 256, 256>>>(po_, pl_, attno_);
        gemm(attno_, nullptr, wo + (size_t)i * CC * CC, bo + (size_t)i * CC,
             h_, pre2_, NN, CC, CC, 0, st_ + 2 * CC, st_ + 3 * CC, 0);

        // --- side stream: CSR build (layer 0) + GINE branch ---
        cudaStreamWaitEvent(s1, evF[i], 0);
        if (i == 0) {
            decode_idx<<<(EE + 255) / 256, 256, 0, s1>>>(ei, ea);
            csr_scan<<<1, 1024, 0, s1>>>();
            csr_fill<<<(EE + 255) / 256, 256, 0, s1>>>();
        }
        gine_agg<<<NN / 8, 256, 0, s1>>>(h_, emb, agg_);
        gemm(agg_, h_, gw1, gb1, nullptr, t1_, NN, CC, CC, 1, nullptr, nullptr, s1);
        gemm(t1_, nullptr, gw2, gb2, h_, pre1_, NN, CC, CC, 0, st_ + 0, st_ + CC, s1);
        cudaEventRecord(evJ[i], s1);

        cudaStreamWaitEvent(0, evJ[i], 0);

        // --- merge + FFN (main stream) ---
        bn2_add<<<(NCEL + 255) / 256, 256>>>(pre1_, pre2_, st_,
                                             bng + (size_t)i * 3 * CC, bnb + (size_t)i * 3 * CC,
                                             bng + (size_t)i * 3 * CC + CC, bnb + (size_t)i * 3 * CC + CC,
                                             outb_);
        gemm(outb_, nullptr, fw1 + (size_t)i * CC * 2 * CC, fb1 + (size_t)i * 2 * CC,
             nullptr, t2_, NN, 2 * CC, CC, 1, nullptr, nullptr, 0);
        gemm(t2_, nullptr, fw2 + (size_t)i * 2 * CC * CC, fb2 + (size_t)i * CC,
             outb_, pre3_, NN, CC, 2 * CC, 0, st_ + 4 * CC, st_ + 5 * CC, 0);
        bn_apply<<<(NCEL + 255) / 256, 256>>>(pre3_, st_ + 4 * CC, st_ + 5 * CC,
                                              bng + (size_t)i * 3 * CC + 2 * CC,
                                              bnb + (size_t)i * 3 * CC + 2 * CC, h_);
    }

    gemm(h_, nullptr, w_o, b_o, nullptr, y_, NN, CC, CC, 0, nullptr, nullptr, 0);
    out_ln<<<NN / 4, 128>>>(y_, lng, lnb, out);
}

// round 16
// speedup vs baseline: 1.0741x; 1.0741x over previous
#include <cuda_runtime.h>
#include <cuda_bf16.h>
#include <cstdint>

#define NN 4096
#define CC 96
#define EE 131072
#define NHEADS 4
#define DH 24
#define SPLITS 8

typedef unsigned long long u64;

// ---------------- scratch ----------------
__device__ float g_h[NN*CC];
__device__ float g_agg[NN*CC];
__device__ float g_t1[NN*CC];
__device__ float g_pre1[NN*CC];
__device__ float g_qkv[NN*3*CC];
__device__ float g_attno[NN*CC];
__device__ float g_pre2[NN*CC];
__device__ float g_outb[NN*CC];
__device__ float g_t2[NN*2*CC];
__device__ float g_pre3[NN*CC];
__device__ float g_y[NN*CC];
__device__ float g_stats[12*CC];
__device__ int   g_src[EE];
__device__ int   g_dst[EE];
__device__ int   g_eat[EE];
__device__ int   g_flags[2];
__device__ int   g_cnt[NN];
__device__ int   g_off[NN+1];
__device__ int   g_cur[NN];
__device__ int   g_csrc[EE];
__device__ int   g_ceat[EE];
__device__ float g_po[SPLITS*NHEADS*NN*DH];
__device__ float g_pl[SPLITS*NHEADS*NN];
// packed attention operands: [h*24+d][key]
__device__ unsigned       g_kt[NHEADS*DH*NN];
__device__ unsigned short g_vh[NHEADS*DH*NN];

// ---------------- mma.sync helpers ----------------
__device__ __forceinline__ unsigned f2tf32(float f) {
    unsigned r; asm("cvt.rna.tf32.f32 %0, %1;" : "=r"(r) : "f"(f)); return r;
}
__device__ __forceinline__ unsigned pkbf(float lo, float hi) {
    unsigned r; asm("cvt.rn.bf16x2.f32 %0, %1, %2;" : "=r"(r) : "f"(hi), "f"(lo)); return r;
}
__device__ __forceinline__ void mma_tf32(float* c, const unsigned* a, const unsigned* b) {
    asm volatile("mma.sync.aligned.m16n8k8.row.col.f32.tf32.tf32.f32 "
        "{%0,%1,%2,%3}, {%4,%5,%6,%7}, {%8,%9}, {%0,%1,%2,%3};"
        : "+f"(c[0]), "+f"(c[1]), "+f"(c[2]), "+f"(c[3])
        : "r"(a[0]), "r"(a[1]), "r"(a[2]), "r"(a[3]), "r"(b[0]), "r"(b[1]));
}
__device__ __forceinline__ void mma_bf16(float* c, const unsigned* a, const unsigned* b) {
    asm volatile("mma.sync.aligned.m16n8k16.row.col.f32.bf16.bf16.f32 "
        "{%0,%1,%2,%3}, {%4,%5,%6,%7}, {%8,%9}, {%0,%1,%2,%3};"
        : "+f"(c[0]), "+f"(c[1]), "+f"(c[2]), "+f"(c[3])
        : "r"(a[0]), "r"(a[1]), "r"(a[2]), "r"(a[3]), "r"(b[0]), "r"(b[1]));
}
__device__ __forceinline__ void cp16(unsigned dst_smem, const void* src) {
    asm volatile("cp.async.cg.shared.global [%0], [%1], 16;" :: "r"(dst_smem), "l"(src));
}

// ---------------- prologue ----------------
__global__ void prep(const unsigned* __restrict__ ei, const unsigned* __restrict__ ea) {
    int t = blockIdx.x * blockDim.x + threadIdx.x;
    if (blockIdx.x == 0 && threadIdx.x < 32) {
        int lane = threadIdx.x;
        unsigned v1 = (lane < 16) ? ei[2 * lane + 1] : 0u;
        unsigned v2 = (lane < 16) ? ea[2 * lane + 1] : 0u;
        unsigned b1 = __ballot_sync(0xffffffffu, v1 != 0u);
        unsigned b2 = __ballot_sync(0xffffffffu, v2 != 0u);
        if (lane == 0) { g_flags[0] = (b1 == 0u); g_flags[1] = (b2 == 0u); }
    }
    if (t < NN) g_cnt[t] = 0;
    if (t < 12 * CC) g_stats[t] = 0.f;
}

__global__ void decode_idx(const void* __restrict__ ei, const void* __restrict__ ea) {
    int e = blockIdx.x * blockDim.x + threadIdx.x;
    if (e >= EE) return;
    int s, d, a;
    if (g_flags[0]) {
        const long long* p = (const long long*)ei;
        s = (int)p[e]; d = (int)p[EE + e];
    } else {
        const int* p = (const int*)ei;
        s = p[e]; d = p[EE + e];
    }
    if (g_flags[1]) {
        const long long* p = (const long long*)ea;
        a = (int)p[e];
    } else {
        const int* p = (const int*)ea;
        a = p[e];
    }
    g_src[e] = s; g_dst[e] = d; g_eat[e] = a;
    atomicAdd(&g_cnt[d], 1);
}

// shfl-based two-level scan (1024 threads, 4 elems/thread)
__global__ __launch_bounds__(1024) void csr_scan() {
    __shared__ int wsum[32];
    int t = threadIdx.x;
    int lane = t & 31, wid = t >> 5;
    int c0 = g_cnt[4*t], c1 = g_cnt[4*t+1], c2 = g_cnt[4*t+2], c3 = g_cnt[4*t+3];
    int s = c0 + c1 + c2 + c3;
    int v = s;
    #pragma unroll
    for (int o = 1; o < 32; o <<= 1) {
        int n = __shfl_up_sync(0xffffffffu, v, o);
        if (lane >= o) v += n;
    }
    if (lane == 31) wsum[wid] = v;
    __syncthreads();
    if (wid == 0) {
        int x = wsum[lane];
        #pragma unroll
        for (int o = 1; o < 32; o <<= 1) {
            int n = __shfl_up_sync(0xffffffffu, x, o);
            if (lane >= o) x += n;
        }
        wsum[lane] = x;
    }
    __syncthreads();
    int incl = v + (wid ? wsum[wid - 1] : 0);
    int base = incl - s;
    g_off[4*t] = base;            g_cur[4*t] = base;
    g_off[4*t+1] = base+c0;       g_cur[4*t+1] = base+c0;
    g_off[4*t+2] = base+c0+c1;    g_cur[4*t+2] = base+c0+c1;
    g_off[4*t+3] = base+c0+c1+c2; g_cur[4*t+3] = base+c0+c1+c2;
    if (t == 1023) g_off[NN] = incl;
}
__global__ void csr_fill() {
    int e = blockIdx.x * blockDim.x + threadIdx.x;
    if (e >= EE) return;
    int pos = atomicAdd(&g_cur[g_dst[e]], 1);
    g_csrc[pos] = g_src[e];
    g_ceat[pos] = g_eat[e];
}

// ---------------- GINE aggregate ----------------
__global__ __launch_bounds__(256) void gine_agg(const float* __restrict__ h,
                                                const float* __restrict__ emb,
                                                float* __restrict__ agg) {
    int warp = (blockIdx.x * 256 + threadIdx.x) >> 5;
    int lane = threadIdx.x & 31;
    if (warp >= NN) return;
    int beg = g_off[warp], end = g_off[warp + 1];
    float a0 = 0.f, a1 = 0.f, a2 = 0.f;
    for (int i = beg; i < end; i++) {
        int src = g_csrc[i], et = g_ceat[i];
        const float* hp = h + (size_t)src * CC;
        const float* ep = emb + (size_t)et * CC;
        a0 += fmaxf(hp[lane]      + ep[lane],      0.f);
        a1 += fmaxf(hp[lane + 32] + ep[lane + 32], 0.f);
        a2 += fmaxf(hp[lane + 64] + ep[lane + 64], 0.f);
    }
    float* ap = agg + (size_t)warp * CC;
    ap[lane] = a0; ap[lane + 32] = a1; ap[lane + 64] = a2;
}

// ---------------- 3xTF32 tensor-core GEMM with fused epilogue ----------------
__global__ __launch_bounds__(128) void tgemm(
    const float* __restrict__ A, const float* __restrict__ A2,
    const float* __restrict__ W, const float* __restrict__ bias,
    const float* __restrict__ res, float* __restrict__ C,
    int M, int N, int K, int relu,
    float* __restrict__ st_s, float* __restrict__ st_s2,
    unsigned* __restrict__ kt_out, unsigned short* __restrict__ vh_out)
{
    __shared__ __align__(16) unsigned Bhi[32 * 40];
    __shared__ __align__(16) unsigned Blo[32 * 40];
    __shared__ float Ssum[4][32];
    __shared__ float Ssq[4][32];
    const int tid = threadIdx.x;
    const int w = tid >> 5, lane = tid & 31;
    const int tg = lane >> 2, tq = lane & 3;
    const int row0 = blockIdx.y * 64 + w * 16;
    const int col0 = blockIdx.x * 32;

    float c[4][4];
    #pragma unroll
    for (int nt = 0; nt < 4; nt++)
        #pragma unroll
        for (int r = 0; r < 4; r++) c[nt][r] = 0.f;

    for (int k0 = 0; k0 < K; k0 += 32) {
        __syncthreads();
        #pragma unroll
        for (int j = 0; j < 2; j++) {
            int idx = tid + j * 128;
            int r = idx >> 3, c4 = (idx & 7) * 4;
            float4 v = *(const float4*)(W + (size_t)(k0 + r) * N + col0 + c4);
            unsigned h0 = f2tf32(v.x), h1 = f2tf32(v.y), h2 = f2tf32(v.z), h3 = f2tf32(v.w);
            *(uint4*)&Bhi[r * 40 + c4] = make_uint4(h0, h1, h2, h3);
            *(uint4*)&Blo[r * 40 + c4] = make_uint4(
                f2tf32(v.x - __uint_as_float(h0)), f2tf32(v.y - __uint_as_float(h1)),
                f2tf32(v.z - __uint_as_float(h2)), f2tf32(v.w - __uint_as_float(h3)));
        }
        __syncthreads();
        #pragma unroll
        for (int kc = 0; kc < 4; kc++) {
            const float* ap0 = A + (size_t)(row0 + tg) * K + k0 + kc * 8;
            const float* ap1 = A + (size_t)(row0 + tg + 8) * K + k0 + kc * 8;
            float av[4];
            av[0] = ap0[tq]; av[1] = ap1[tq]; av[2] = ap0[tq + 4]; av[3] = ap1[tq + 4];
            if (A2) {
                const float* bp0 = A2 + (size_t)(row0 + tg) * K + k0 + kc * 8;
                const float* bp1 = A2 + (size_t)(row0 + tg + 8) * K + k0 + kc * 8;
                av[0] += bp0[tq]; av[1] += bp1[tq]; av[2] += bp0[tq + 4]; av[3] += bp1[tq + 4];
            }
            unsigned ahi[4], alo[4];
            #pragma unroll
            for (int r = 0; r < 4; r++) {
                ahi[r] = f2tf32(av[r]);
                alo[r] = f2tf32(av[r] - __uint_as_float(ahi[r]));
            }
            const int kr0 = (kc * 8 + tq) * 40;
            const int kr1 = (kc * 8 + tq + 4) * 40;
            #pragma unroll
            for (int nt = 0; nt < 4; nt++) {
                unsigned bh[2], bl[2];
                bh[0] = Bhi[kr0 + nt * 8 + tg]; bh[1] = Bhi[kr1 + nt * 8 + tg];
                bl[0] = Blo[kr0 + nt * 8 + tg]; bl[1] = Blo[kr1 + nt * 8 + tg];
                mma_tf32(c[nt], ahi, bh);
                mma_tf32(c[nt], ahi, bl);
                mma_tf32(c[nt], alo, bh);
            }
        }
    }

    float myS[8], myQ[8];
    #pragma unroll
    for (int nt = 0; nt < 4; nt++) {
        int cc0 = col0 + nt * 8 + 2 * tq;
        float b0 = bias[cc0], b1 = bias[cc0 + 1];
        float v00 = c[nt][0] + b0, v01 = c[nt][1] + b1;
        float v10 = c[nt][2] + b0, v11 = c[nt][3] + b1;
        if (res) {
            float2 r0v = *(const float2*)(res + (size_t)(row0 + tg) * N + cc0);
            float2 r1v = *(const float2*)(res + (size_t)(row0 + tg + 8) * N + cc0);
            v00 += r0v.x; v01 += r0v.y; v10 += r1v.x; v11 += r1v.y;
        }
        if (relu) {
            v00 = fmaxf(v00, 0.f); v01 = fmaxf(v01, 0.f);
            v10 = fmaxf(v10, 0.f); v11 = fmaxf(v11, 0.f);
        }
        *(float2*)(C + (size_t)(row0 + tg) * N + cc0) = make_float2(v00, v01);
        *(float2*)(C + (size_t)(row0 + tg + 8) * N + cc0) = make_float2(v10, v11);

        if (kt_out && cc0 >= CC) {
            #pragma unroll
            for (int jj = 0; jj < 2; jj++) {
                int col = cc0 + jj;
                float va = jj ? v01 : v00;
                float vb = jj ? v11 : v10;
                if (col < 2 * CC) {
                    kt_out[(size_t)(col - CC) * NN + row0 + tg] = f2tf32(va);
                    kt_out[(size_t)(col - CC) * NN + row0 + tg + 8] = f2tf32(vb);
                } else {
                    vh_out[(size_t)(col - 2 * CC) * NN + row0 + tg] =
                        __bfloat16_as_ushort(__float2bfloat16(va));
                    vh_out[(size_t)(col - 2 * CC) * NN + row0 + tg + 8] =
                        __bfloat16_as_ushort(__float2bfloat16(vb));
                }
            }
        }

        myS[nt * 2] = v00 + v10;           myS[nt * 2 + 1] = v01 + v11;
        myQ[nt * 2] = v00 * v00 + v10 * v10; myQ[nt * 2 + 1] = v01 * v01 + v11 * v11;
    }

    if (st_s) {
        #pragma unroll
        for (int i = 0; i < 8; i++) {
            #pragma unroll
            for (int o = 4; o <= 16; o <<= 1) {
                myS[i] += __shfl_xor_sync(0xffffffffu, myS[i], o);
                myQ[i] += __shfl_xor_sync(0xffffffffu, myQ[i], o);
            }
        }
        if (tg == 0) {
            #pragma unroll
            for (int nt = 0; nt < 4; nt++) {
                Ssum[w][nt * 8 + 2 * tq] = myS[nt * 2];
                Ssum[w][nt * 8 + 2 * tq + 1] = myS[nt * 2 + 1];
                Ssq[w][nt * 8 + 2 * tq] = myQ[nt * 2];
                Ssq[w][nt * 8 + 2 * tq + 1] = myQ[nt * 2 + 1];
            }
        }
        __syncthreads();
        if (tid < 32) {
            float a = Ssum[0][tid] + Ssum[1][tid] + Ssum[2][tid] + Ssum[3][tid];
            float b = Ssq[0][tid] + Ssq[1][tid] + Ssq[2][tid] + Ssq[3][tid];
            atomicAdd(&st_s[col0 + tid], a);
            atomicAdd(&st_s2[col0 + tid], b);
        }
    }
}

// ---------------- mma.sync flash attention (cp.async double-buffered, half-tiles) ----------------
#define QSCALE 0.2944858445807166f
#define NTILES ((NN / SPLITS) / 64)

__global__ __launch_bounds__(128) void flash_mma(const float* __restrict__ qkv,
                                                 const unsigned* __restrict__ kt,
                                                 const unsigned short* __restrict__ vh,
                                                 float* __restrict__ po,
                                                 float* __restrict__ pl) {
    __shared__ __align__(16) unsigned KtU[2][24 * 72];
    __shared__ __align__(16) unsigned short Vh[2][24 * 72];
    const int h   = blockIdx.y;
    const int q0  = blockIdx.x * 128;
    const int sp  = blockIdx.z;
    const int tid = threadIdx.x;
    const int w   = tid >> 5;
    const int lane = tid & 31;
    const int tg = lane >> 2, tq = lane & 3;

    const unsigned* ktb0 = kt + (size_t)h * DH * NN + sp * (NN / SPLITS);
    const unsigned short* vhb0 = vh + (size_t)h * DH * NN + sp * (NN / SPLITS);

    auto stage = [&](int t, int buf) {
        const unsigned* ktb = ktb0 + t * 64;
        const unsigned short* vhb = vhb0 + t * 64;
        unsigned kbase = (unsigned)__cvta_generic_to_shared(&KtU[buf][0]);
        unsigned vbase = (unsigned)__cvta_generic_to_shared(&Vh[buf][0]);
        #pragma unroll
        for (int ii = 0; ii < 3; ii++) {              // K ops 0..383
            int idx = tid + ii * 128;
            int row = idx >> 4, q = idx & 15;
            cp16(kbase + (row * 72 + q * 4) * 4, ktb + (size_t)row * NN + q * 4);
        }
        {                                             // V ops 0..127
            int row = tid >> 3, q = tid & 7;
            cp16(vbase + (row * 72 + q * 8) * 2, vhb + (size_t)row * NN + q * 8);
        }
        if (tid < 64) {                               // V ops 128..191
            int idx = 128 + tid;
            int row = idx >> 3, q = idx & 7;
            cp16(vbase + (row * 72 + q * 8) * 2, vhb + (size_t)row * NN + q * 8);
        }
        asm volatile("cp.async.commit_group;" ::: "memory");
    };

    unsigned QA[2][3][4];
    #pragma unroll
    for (int mi = 0; mi < 2; mi++) {
        const float* qp0 = qkv + (size_t)(q0 + 32 * w + 16 * mi + tg) * (3 * CC) + h * DH;
        const float* qp1 = qp0 + (size_t)8 * (3 * CC);
        #pragma unroll
        for (int kc = 0; kc < 3; kc++) {
            QA[mi][kc][0] = f2tf32(qp0[kc * 8 + tq] * QSCALE);
            QA[mi][kc][1] = f2tf32(qp1[kc * 8 + tq] * QSCALE);
            QA[mi][kc][2] = f2tf32(qp0[kc * 8 + tq + 4] * QSCALE);
            QA[mi][kc][3] = f2tf32(qp1[kc * 8 + tq + 4] * QSCALE);
        }
    }

    float OC[2][3][4];
    #pragma unroll
    for (int mi = 0; mi < 2; mi++)
        #pragma unroll
        for (int n = 0; n < 3; n++)
            #pragma unroll
            for (int r = 0; r < 4; r++) OC[mi][n][r] = 0.f;
    float lacc[2][2] = {{0.f, 0.f}, {0.f, 0.f}};

    stage(0, 0);

    for (int t = 0; t < NTILES; t++) {
        const int buf = t & 1;
        if (t + 1 < NTILES) {
            stage(t + 1, buf ^ 1);
            asm volatile("cp.async.wait_group 1;" ::: "memory");
        } else {
            asm volatile("cp.async.wait_group 0;" ::: "memory");
        }
        __syncthreads();

        #pragma unroll
        for (int kh = 0; kh < 2; kh++) {            // two 32-key halves
            float SC[2][4][4];
            #pragma unroll
            for (int mi = 0; mi < 2; mi++)
                #pragma unroll
                for (int nt = 0; nt < 4; nt++)
                    #pragma unroll
                    for (int r = 0; r < 4; r++) SC[mi][nt][r] = 0.f;

            #pragma unroll
            for (int nt = 0; nt < 4; nt++) {
                const int nc = kh * 32 + nt * 8 + tg;
                unsigned bB[3][2];
                #pragma unroll
                for (int kc = 0; kc < 3; kc++) {
                    bB[kc][0] = KtU[buf][(kc * 8 + tq) * 72 + nc];
                    bB[kc][1] = KtU[buf][(kc * 8 + tq + 4) * 72 + nc];
                }
                #pragma unroll
                for (int kc = 0; kc < 3; kc++) {
                    mma_tf32(SC[0][nt], QA[0][kc], bB[kc]);
                    mma_tf32(SC[1][nt], QA[1][kc], bB[kc]);
                }
            }

            #pragma unroll
            for (int mi = 0; mi < 2; mi++)
                #pragma unroll
                for (int nt = 0; nt < 4; nt++)
                    #pragma unroll
                    for (int r = 0; r < 4; r++) {
                        float e;
                        asm("ex2.approx.ftz.f32 %0, %1;" : "=f"(e) : "f"(SC[mi][nt][r]));
                        SC[mi][nt][r] = e;
                        lacc[mi][r >> 1] += e;
                    }

            unsigned PA[2][2][4];
            #pragma unroll
            for (int mi = 0; mi < 2; mi++)
                #pragma unroll
                for (int kc4 = 0; kc4 < 2; kc4++) {
                    PA[mi][kc4][0] = pkbf(SC[mi][2 * kc4][0],     SC[mi][2 * kc4][1]);
                    PA[mi][kc4][1] = pkbf(SC[mi][2 * kc4][2],     SC[mi][2 * kc4][3]);
                    PA[mi][kc4][2] = pkbf(SC[mi][2 * kc4 + 1][0], SC[mi][2 * kc4 + 1][1]);
                    PA[mi][kc4][3] = pkbf(SC[mi][2 * kc4 + 1][2], SC[mi][2 * kc4 + 1][3]);
                }

            #pragma unroll
            for (int kc4 = 0; kc4 < 2; kc4++) {
                #pragma unroll
                for (int n = 0; n < 3; n++) {
                    int drow = n * 8 + tg;
                    int col = kh * 32 + kc4 * 16 + 2 * tq;
                    unsigned bh[2];
                    bh[0] = *(const unsigned*)&Vh[buf][drow * 72 + col];
                    bh[1] = *(const unsigned*)&Vh[buf][drow * 72 + col + 8];
                    mma_bf16(OC[0][n], PA[0][kc4], bh);
                    mma_bf16(OC[1][n], PA[1][kc4], bh);
                }
            }
        }
        __syncthreads();
    }

    #pragma unroll
    for (int mi = 0; mi < 2; mi++)
        #pragma unroll
        for (int hi = 0; hi < 2; hi++) {
            float v = lacc[mi][hi];
            v += __shfl_xor_sync(0xffffffffu, v, 1);
            v += __shfl_xor_sync(0xffffffffu, v, 2);
            lacc[mi][hi] = v;
        }

    const int base = (sp * NHEADS + h) * NN;
    #pragma unroll
    for (int mi = 0; mi < 2; mi++) {
        int r0 = q0 + 32 * w + 16 * mi + tg;
        int r1 = r0 + 8;
        if (tq == 0) {
            pl[base + r0] = lacc[mi][0];
            pl[base + r1] = lacc[mi][1];
        }
        #pragma unroll
        for (int n = 0; n < 3; n++) {
            float2 v0 = make_float2(OC[mi][n][0], OC[mi][n][1]);
            float2 v1 = make_float2(OC[mi][n][2], OC[mi][n][3]);
            *(float2*)(po + ((size_t)(base + r0)) * DH + n * 8 + 2 * tq) = v0;
            *(float2*)(po + ((size_t)(base + r1)) * DH + n * 8 + 2 * tq) = v1;
        }
    }
}

__global__ void flash_combine(const float* __restrict__ po, const float* __restrict__ pl,
                              float* __restrict__ outp) {
    int t = blockIdx.x * blockDim.x + threadIdx.x;
    if (t >= NN * NHEADS) return;
    int q = t & (NN - 1);
    int h = t >> 12;
    float L = 0.f;
    #pragma unroll
    for (int s = 0; s < SPLITS; s++) L += pl[(s * NHEADS + h) * NN + q];
    float inv = 1.f / L;
    float* op = outp + (size_t)q * CC + h * DH;
    #pragma unroll
    for (int d = 0; d < DH; d += 4) {
        float4 acc = make_float4(0.f, 0.f, 0.f, 0.f);
        #pragma unroll
        for (int s = 0; s < SPLITS; s++) {
            const float4 v = *(const float4*)(po + ((size_t)(s * NHEADS + h) * NN + q) * DH + d);
            acc.x += v.x; acc.y += v.y; acc.z += v.z; acc.w += v.w;
        }
        acc.x *= inv; acc.y *= inv; acc.z *= inv; acc.w *= inv;
        *(float4*)(op + d) = acc;
    }
}

// ---------------- BN elementwise ----------------
__global__ void bn2_add(const float* __restrict__ p1, const float* __restrict__ p2,
                        const float* __restrict__ st,
                        const float* __restrict__ g1, const float* __restrict__ b1,
                        const float* __restrict__ g2, const float* __restrict__ b2,
                        float* __restrict__ out) {
    int i = blockIdx.x * blockDim.x + threadIdx.x;
    if (i >= NN * CC) return;
    int c = i % CC;
    const float invn = 1.f / NN;
    float m1 = st[c] * invn;
    float v1 = st[CC + c] * invn - m1 * m1;
    float m2 = st[2 * CC + c] * invn;
    float v2 = st[3 * CC + c] * invn - m2 * m2;
    float o = (p1[i] - m1) * rsqrtf(v1 + 1e-5f) * g1[c] + b1[c]
            + (p2[i] - m2) * rsqrtf(v2 + 1e-5f) * g2[c] + b2[c];
    out[i] = o;
}

__global__ void bn_apply(const float* __restrict__ p, const float* __restrict__ s,
                         const float* __restrict__ s2, const float* __restrict__ g,
                         const float* __restrict__ b, float* __restrict__ o) {
    int i = blockIdx.x * blockDim.x + threadIdx.x;
    if (i >= NN * CC) return;
    int c = i % CC;
    const float invn = 1.f / NN;
    float m = s[c] * invn;
    float v = s2[c] * invn - m * m;
    o[i] = (p[i] - m) * rsqrtf(v + 1e-5f) * g[c] + b[c];
}

// ---------------- final per-row LayerNorm ----------------
__global__ void out_ln(const float* __restrict__ y, const float* __restrict__ g,
                       const float* __restrict__ b, float* __restrict__ out) {
    int lane = threadIdx.x & 31;
    int warp = threadIdx.x >> 5;
    int row  = blockIdx.x * 4 + warp;
    const float* yr = y + (size_t)row * CC;
    float v0 = yr[lane], v1 = yr[lane + 32], v2 = yr[lane + 64];
    float s = v0 + v1 + v2;
    #pragma unroll
    for (int o = 16; o; o >>= 1) s += __shfl_xor_sync(0xffffffffu, s, o);
    float mean = s * (1.f / 96.f);
    float d0 = v0 - mean, d1 = v1 - mean, d2 = v2 - mean;
    float qv = d0 * d0 + d1 * d1 + d2 * d2;
    #pragma unroll
    for (int o = 16; o; o >>= 1) qv += __shfl_xor_sync(0xffffffffu, qv, o);
    float inv = rsqrtf(qv * (1.f / 96.f) + 1e-5f);
    float* orow = out + (size_t)row * CC;
    orow[lane]      = d0 * inv * g[lane]      + b[lane];
    orow[lane + 32] = d1 * inv * g[lane + 32] + b[lane + 32];
    orow[lane + 64] = d2 * inv * g[lane + 64] + b[lane + 64];
}

// ---------------- launch ----------------
extern "C" void kernel_launch(void* const* d_in, const int* in_sizes, int n_in,
                              void* d_out, int out_size) {
    const float*     x    = (const float*)d_in[0];
    const void*      ei   = d_in[1];
    const void*      ea   = d_in[2];
    const float*     w_in = (const float*)d_in[3];
    const float*     b_in = (const float*)d_in[4];
    const float*     emb  = (const float*)d_in[5];
    const float*     gw1  = (const float*)d_in[6];
    const float*     gb1  = (const float*)d_in[7];
    const float*     gw2  = (const float*)d_in[8];
    const float*     gb2  = (const float*)d_in[9];
    const float*     wqkv = (const float*)d_in[10];
    const float*     bqkv = (const float*)d_in[11];
    const float*     wo   = (const float*)d_in[12];
    const float*     bo   = (const float*)d_in[13];
    const float*     bng  = (const float*)d_in[14];
    const float*     bnb  = (const float*)d_in[15];
    const float*     fw1  = (const float*)d_in[16];
    const float*     fb1  = (const float*)d_in[17];
    const float*     fw2  = (const float*)d_in[18];
    const float*     fb2  = (const float*)d_in[19];
    const float*     w_o  = (const float*)d_in[20];
    const float*     b_o  = (const float*)d_in[21];
    const float*     lng  = (const float*)d_in[22];
    const float*     lnb  = (const float*)d_in[23];
    float* out = (float*)d_out;

    float *h_, *agg_, *t1_, *pre1_, *qkv_, *attno_, *pre2_, *outb_, *t2_, *pre3_, *y_, *stA_;
    float *po_, *pl_;
    unsigned* kt_;
    unsigned short* vh_;
    cudaGetSymbolAddress((void**)&h_,    g_h);
    cudaGetSymbolAddress((void**)&agg_,  g_agg);
    cudaGetSymbolAddress((void**)&t1_,   g_t1);
    cudaGetSymbolAddress((void**)&pre1_, g_pre1);
    cudaGetSymbolAddress((void**)&qkv_,  g_qkv);
    cudaGetSymbolAddress((void**)&attno_,g_attno);
    cudaGetSymbolAddress((void**)&pre2_, g_pre2);
    cudaGetSymbolAddress((void**)&outb_, g_outb);
    cudaGetSymbolAddress((void**)&t2_,   g_t2);
    cudaGetSymbolAddress((void**)&pre3_, g_pre3);
    cudaGetSymbolAddress((void**)&y_,    g_y);
    cudaGetSymbolAddress((void**)&stA_,  g_stats);
    cudaGetSymbolAddress((void**)&po_,   g_po);
    cudaGetSymbolAddress((void**)&pl_,   g_pl);
    cudaGetSymbolAddress((void**)&kt_,   g_kt);
    cudaGetSymbolAddress((void**)&vh_,   g_vh);

    cudaStream_t s1;
    cudaStreamCreateWithFlags(&s1, cudaStreamNonBlocking);
    cudaEvent_t evF[2], evJ[2];
    for (int i = 0; i < 2; i++) {
        cudaEventCreateWithFlags(&evF[i], cudaEventDisableTiming);
        cudaEventCreateWithFlags(&evJ[i], cudaEventDisableTiming);
    }

    auto gemm = [&](const float* A, const float* A2, const float* W, const float* bias,
                    const float* res, float* Cp, int M, int Nc, int K, int relu,
                    float* ss, float* ss2, cudaStream_t st,
                    unsigned* kto = nullptr, unsigned short* vho = nullptr) {
        dim3 grid(Nc / 32, M / 64);
        tgemm<<<grid, 128, 0, st>>>(A, A2, W, bias, res, Cp, M, Nc, K, relu, ss, ss2, kto, vho);
    };

    const int NCEL = NN * CC;

    prep<<<16, 256>>>((const unsigned*)ei, (const unsigned*)ea);
    gemm(x, nullptr, w_in, b_in, nullptr, h_, NN, CC, 64, 0, nullptr, nullptr, 0);

    for (int i = 0; i < 2; i++) {
        float* st_ = stA_ + (size_t)i * 6 * CC;

        cudaEventRecord(evF[i], 0);

        // --- main stream: attention branch ---
        gemm(h_, nullptr, wqkv + (size_t)i * CC * 3 * CC, bqkv + (size_t)i * 3 * CC,
             nullptr, qkv_, NN, 3 * CC, CC, 0, nullptr, nullptr, 0, kt_, vh_);
        flash_mma<<<dim3(NN / 128, NHEADS, SPLITS), 128>>>(qkv_, kt_, vh_, po_, pl_);
        flash_combine<<<(NN * NHEADS + 255) / 256, 256>>>(po_, pl_, attno_);
        gemm(attno_, nullptr, wo + (size_t)i * CC * CC, bo + (size_t)i * CC,
             h_, pre2_, NN, CC, CC, 0, st_ + 2 * CC, st_ + 3 * CC, 0);

        // --- side stream: CSR build (layer 0) + GINE branch ---
        cudaStreamWaitEvent(s1, evF[i], 0);
        if (i == 0) {
            decode_idx<<<(EE + 255) / 256, 256, 0, s1>>>(ei, ea);
            csr_scan<<<1, 1024, 0, s1>>>();
            csr_fill<<<(EE + 255) / 256, 256, 0, s1>>>();
        }
        gine_agg<<<NN / 8, 256, 0, s1>>>(h_, emb, agg_);
        gemm(agg_, h_, gw1, gb1, nullptr, t1_, NN, CC, CC, 1, nullptr, nullptr, s1);
        gemm(t1_, nullptr, gw2, gb2, h_, pre1_, NN, CC, CC, 0, st_ + 0, st_ + CC, s1);
        cudaEventRecord(evJ[i], s1);

        cudaStreamWaitEvent(0, evJ[i], 0);

        // --- merge + FFN (main stream) ---
        bn2_add<<<(NCEL + 255) / 256, 256>>>(pre1_, pre2_, st_,
                                             bng + (size_t)i * 3 * CC, bnb + (size_t)i * 3 * CC,
                                             bng + (size_t)i * 3 * CC + CC, bnb + (size_t)i * 3 * CC + CC,
                                             outb_);
        gemm(outb_, nullptr, fw1 + (size_t)i * CC * 2 * CC, fb1 + (size_t)i * 2 * CC,
             nullptr, t2_, NN, 2 * CC, CC, 1, nullptr, nullptr, 0);
        gemm(t2_, nullptr, fw2 + (size_t)i * 2 * CC * CC, fb2 + (size_t)i * CC,
             outb_, pre3_, NN, CC, 2 * CC, 0, st_ + 4 * CC, st_ + 5 * CC, 0);
        bn_apply<<<(NCEL + 255) / 256, 256>>>(pre3_, st_ + 4 * CC, st_ + 5 * CC,
                                              bng + (size_t)i * 3 * CC + 2 * CC,
                                              bnb + (size_t)i * 3 * CC + 2 * CC, h_);
    }

    gemm(h_, nullptr, w_o, b_o, nullptr, y_, NN, CC, CC, 0, nullptr, nullptr, 0);
    out_ln<<<NN / 4, 128>>>(y_, lng, lnb, out);
}

// round 17
// speedup vs baseline: 1.0937x; 1.0183x over previous
#include <cuda_runtime.h>
#include <cuda_bf16.h>
#include <cstdint>

#define NN 4096
#define CC 96
#define EE 131072
#define NHEADS 4
#define DH 24
#define SPLITS 8

typedef unsigned long long u64;

// ---------------- scratch ----------------
__device__ float g_h[NN*CC];
__device__ float g_agg[NN*CC];
__device__ float g_t1[NN*CC];
__device__ float g_pre1[NN*CC];
__device__ float g_qkv[NN*3*CC];
__device__ float g_attno[NN*CC];
__device__ float g_pre2[NN*CC];
__device__ float g_outb[NN*CC];
__device__ float g_t2[NN*2*CC];
__device__ float g_pre3[NN*CC];
__device__ float g_y[NN*CC];
__device__ float g_stats[12*CC];
__device__ int   g_src[EE];
__device__ int   g_dst[EE];
__device__ int   g_eat[EE];
__device__ int   g_flags[2];
__device__ int   g_cnt[NN];
__device__ int   g_off[NN+1];
__device__ int   g_cur[NN];
__device__ int   g_csrc[EE];
__device__ int   g_ceat[EE];
__device__ float g_po[SPLITS*NHEADS*NN*DH];
__device__ float g_pl[SPLITS*NHEADS*NN];
// packed attention operands: [h*24+d][key]
__device__ unsigned       g_kt[NHEADS*DH*NN];
__device__ unsigned short g_vh[NHEADS*DH*NN];

// ---------------- mma.sync helpers ----------------
__device__ __forceinline__ unsigned f2tf32(float f) {
    unsigned r; asm("cvt.rna.tf32.f32 %0, %1;" : "=r"(r) : "f"(f)); return r;
}
__device__ __forceinline__ unsigned pkbf(float lo, float hi) {
    unsigned r; asm("cvt.rn.bf16x2.f32 %0, %1, %2;" : "=r"(r) : "f"(hi), "f"(lo)); return r;
}
__device__ __forceinline__ void mma_tf32(float* c, const unsigned* a, const unsigned* b) {
    asm volatile("mma.sync.aligned.m16n8k8.row.col.f32.tf32.tf32.f32 "
        "{%0,%1,%2,%3}, {%4,%5,%6,%7}, {%8,%9}, {%0,%1,%2,%3};"
        : "+f"(c[0]), "+f"(c[1]), "+f"(c[2]), "+f"(c[3])
        : "r"(a[0]), "r"(a[1]), "r"(a[2]), "r"(a[3]), "r"(b[0]), "r"(b[1]));
}
__device__ __forceinline__ void mma_bf16(float* c, const unsigned* a, const unsigned* b) {
    asm volatile("mma.sync.aligned.m16n8k16.row.col.f32.bf16.bf16.f32 "
        "{%0,%1,%2,%3}, {%4,%5,%6,%7}, {%8,%9}, {%0,%1,%2,%3};"
        : "+f"(c[0]), "+f"(c[1]), "+f"(c[2]), "+f"(c[3])
        : "r"(a[0]), "r"(a[1]), "r"(a[2]), "r"(a[3]), "r"(b[0]), "r"(b[1]));
}
__device__ __forceinline__ void cp16(unsigned dst_smem, const void* src) {
    asm volatile("cp.async.cg.shared.global [%0], [%1], 16;" :: "r"(dst_smem), "l"(src));
}

// ---------------- prologue ----------------
__global__ void prep(const unsigned* __restrict__ ei, const unsigned* __restrict__ ea) {
    int t = blockIdx.x * blockDim.x + threadIdx.x;
    if (blockIdx.x == 0 && threadIdx.x < 32) {
        int lane = threadIdx.x;
        unsigned v1 = (lane < 16) ? ei[2 * lane + 1] : 0u;
        unsigned v2 = (lane < 16) ? ea[2 * lane + 1] : 0u;
        unsigned b1 = __ballot_sync(0xffffffffu, v1 != 0u);
        unsigned b2 = __ballot_sync(0xffffffffu, v2 != 0u);
        if (lane == 0) { g_flags[0] = (b1 == 0u); g_flags[1] = (b2 == 0u); }
    }
    if (t < NN) g_cnt[t] = 0;
    if (t < 12 * CC) g_stats[t] = 0.f;
}

__global__ void decode_idx(const void* __restrict__ ei, const void* __restrict__ ea) {
    int e = blockIdx.x * blockDim.x + threadIdx.x;
    if (e >= EE) return;
    int s, d, a;
    if (g_flags[0]) {
        const long long* p = (const long long*)ei;
        s = (int)p[e]; d = (int)p[EE + e];
    } else {
        const int* p = (const int*)ei;
        s = p[e]; d = p[EE + e];
    }
    if (g_flags[1]) {
        const long long* p = (const long long*)ea;
        a = (int)p[e];
    } else {
        const int* p = (const int*)ea;
        a = p[e];
    }
    g_src[e] = s; g_dst[e] = d; g_eat[e] = a;
    atomicAdd(&g_cnt[d], 1);
}

// shfl-based two-level scan (1024 threads, 4 elems/thread)
__global__ __launch_bounds__(1024) void csr_scan() {
    __shared__ int wsum[32];
    int t = threadIdx.x;
    int lane = t & 31, wid = t >> 5;
    int c0 = g_cnt[4*t], c1 = g_cnt[4*t+1], c2 = g_cnt[4*t+2], c3 = g_cnt[4*t+3];
    int s = c0 + c1 + c2 + c3;
    int v = s;
    #pragma unroll
    for (int o = 1; o < 32; o <<= 1) {
        int n = __shfl_up_sync(0xffffffffu, v, o);
        if (lane >= o) v += n;
    }
    if (lane == 31) wsum[wid] = v;
    __syncthreads();
    if (wid == 0) {
        int x = wsum[lane];
        #pragma unroll
        for (int o = 1; o < 32; o <<= 1) {
            int n = __shfl_up_sync(0xffffffffu, x, o);
            if (lane >= o) x += n;
        }
        wsum[lane] = x;
    }
    __syncthreads();
    int incl = v + (wid ? wsum[wid - 1] : 0);
    int base = incl - s;
    g_off[4*t] = base;            g_cur[4*t] = base;
    g_off[4*t+1] = base+c0;       g_cur[4*t+1] = base+c0;
    g_off[4*t+2] = base+c0+c1;    g_cur[4*t+2] = base+c0+c1;
    g_off[4*t+3] = base+c0+c1+c2; g_cur[4*t+3] = base+c0+c1+c2;
    if (t == 1023) g_off[NN] = incl;
}
__global__ void csr_fill() {
    int e = blockIdx.x * blockDim.x + threadIdx.x;
    if (e >= EE) return;
    int pos = atomicAdd(&g_cur[g_dst[e]], 1);
    g_csrc[pos] = g_src[e];
    g_ceat[pos] = g_eat[e];
}

// ---------------- GINE aggregate ----------------
__global__ __launch_bounds__(256) void gine_agg(const float* __restrict__ h,
                                                const float* __restrict__ emb,
                                                float* __restrict__ agg) {
    int warp = (blockIdx.x * 256 + threadIdx.x) >> 5;
    int lane = threadIdx.x & 31;
    if (warp >= NN) return;
    int beg = g_off[warp], end = g_off[warp + 1];
    float a0 = 0.f, a1 = 0.f, a2 = 0.f;
    for (int i = beg; i < end; i++) {
        int src = g_csrc[i], et = g_ceat[i];
        const float* hp = h + (size_t)src * CC;
        const float* ep = emb + (size_t)et * CC;
        a0 += fmaxf(hp[lane]      + ep[lane],      0.f);
        a1 += fmaxf(hp[lane + 32] + ep[lane + 32], 0.f);
        a2 += fmaxf(hp[lane + 64] + ep[lane + 64], 0.f);
    }
    float* ap = agg + (size_t)warp * CC;
    ap[lane] = a0; ap[lane + 32] = a1; ap[lane + 64] = a2;
}

// ---------------- 3xTF32 tensor-core GEMM with fused epilogue ----------------
__global__ __launch_bounds__(128) void tgemm(
    const float* __restrict__ A, const float* __restrict__ A2,
    const float* __restrict__ W, const float* __restrict__ bias,
    const float* __restrict__ res, float* __restrict__ C,
    int M, int N, int K, int relu,
    float* __restrict__ st_s, float* __restrict__ st_s2,
    unsigned* __restrict__ kt_out, unsigned short* __restrict__ vh_out)
{
    __shared__ __align__(16) unsigned Bhi[32 * 40];
    __shared__ __align__(16) unsigned Blo[32 * 40];
    __shared__ float Ssum[4][32];
    __shared__ float Ssq[4][32];
    const int tid = threadIdx.x;
    const int w = tid >> 5, lane = tid & 31;
    const int tg = lane >> 2, tq = lane & 3;
    const int row0 = blockIdx.y * 64 + w * 16;
    const int col0 = blockIdx.x * 32;

    float c[4][4];
    #pragma unroll
    for (int nt = 0; nt < 4; nt++)
        #pragma unroll
        for (int r = 0; r < 4; r++) c[nt][r] = 0.f;

    for (int k0 = 0; k0 < K; k0 += 32) {
        __syncthreads();
        #pragma unroll
        for (int j = 0; j < 2; j++) {
            int idx = tid + j * 128;
            int r = idx >> 3, c4 = (idx & 7) * 4;
            float4 v = *(const float4*)(W + (size_t)(k0 + r) * N + col0 + c4);
            unsigned h0 = f2tf32(v.x), h1 = f2tf32(v.y), h2 = f2tf32(v.z), h3 = f2tf32(v.w);
            *(uint4*)&Bhi[r * 40 + c4] = make_uint4(h0, h1, h2, h3);
            *(uint4*)&Blo[r * 40 + c4] = make_uint4(
                f2tf32(v.x - __uint_as_float(h0)), f2tf32(v.y - __uint_as_float(h1)),
                f2tf32(v.z - __uint_as_float(h2)), f2tf32(v.w - __uint_as_float(h3)));
        }
        __syncthreads();
        #pragma unroll
        for (int kc = 0; kc < 4; kc++) {
            const float* ap0 = A + (size_t)(row0 + tg) * K + k0 + kc * 8;
            const float* ap1 = A + (size_t)(row0 + tg + 8) * K + k0 + kc * 8;
            float av[4];
            av[0] = ap0[tq]; av[1] = ap1[tq]; av[2] = ap0[tq + 4]; av[3] = ap1[tq + 4];
            if (A2) {
                const float* bp0 = A2 + (size_t)(row0 + tg) * K + k0 + kc * 8;
                const float* bp1 = A2 + (size_t)(row0 + tg + 8) * K + k0 + kc * 8;
                av[0] += bp0[tq]; av[1] += bp1[tq]; av[2] += bp0[tq + 4]; av[3] += bp1[tq + 4];
            }
            unsigned ahi[4], alo[4];
            #pragma unroll
            for (int r = 0; r < 4; r++) {
                ahi[r] = f2tf32(av[r]);
                alo[r] = f2tf32(av[r] - __uint_as_float(ahi[r]));
            }
            const int kr0 = (kc * 8 + tq) * 40;
            const int kr1 = (kc * 8 + tq + 4) * 40;
            #pragma unroll
            for (int nt = 0; nt < 4; nt++) {
                unsigned bh[2], bl[2];
                bh[0] = Bhi[kr0 + nt * 8 + tg]; bh[1] = Bhi[kr1 + nt * 8 + tg];
                bl[0] = Blo[kr0 + nt * 8 + tg]; bl[1] = Blo[kr1 + nt * 8 + tg];
                mma_tf32(c[nt], ahi, bh);
                mma_tf32(c[nt], ahi, bl);
                mma_tf32(c[nt], alo, bh);
            }
        }
    }

    float myS[8], myQ[8];
    #pragma unroll
    for (int nt = 0; nt < 4; nt++) {
        int cc0 = col0 + nt * 8 + 2 * tq;
        float b0 = bias[cc0], b1 = bias[cc0 + 1];
        float v00 = c[nt][0] + b0, v01 = c[nt][1] + b1;
        float v10 = c[nt][2] + b0, v11 = c[nt][3] + b1;
        if (res) {
            float2 r0v = *(const float2*)(res + (size_t)(row0 + tg) * N + cc0);
            float2 r1v = *(const float2*)(res + (size_t)(row0 + tg + 8) * N + cc0);
            v00 += r0v.x; v01 += r0v.y; v10 += r1v.x; v11 += r1v.y;
        }
        if (relu) {
            v00 = fmaxf(v00, 0.f); v01 = fmaxf(v01, 0.f);
            v10 = fmaxf(v10, 0.f); v11 = fmaxf(v11, 0.f);
        }
        *(float2*)(C + (size_t)(row0 + tg) * N + cc0) = make_float2(v00, v01);
        *(float2*)(C + (size_t)(row0 + tg + 8) * N + cc0) = make_float2(v10, v11);

        if (kt_out && cc0 >= CC) {
            #pragma unroll
            for (int jj = 0; jj < 2; jj++) {
                int col = cc0 + jj;
                float va = jj ? v01 : v00;
                float vb = jj ? v11 : v10;
                if (col < 2 * CC) {
                    kt_out[(size_t)(col - CC) * NN + row0 + tg] = f2tf32(va);
                    kt_out[(size_t)(col - CC) * NN + row0 + tg + 8] = f2tf32(vb);
                } else {
                    vh_out[(size_t)(col - 2 * CC) * NN + row0 + tg] =
                        __bfloat16_as_ushort(__float2bfloat16(va));
                    vh_out[(size_t)(col - 2 * CC) * NN + row0 + tg + 8] =
                        __bfloat16_as_ushort(__float2bfloat16(vb));
                }
            }
        }

        myS[nt * 2] = v00 + v10;           myS[nt * 2 + 1] = v01 + v11;
        myQ[nt * 2] = v00 * v00 + v10 * v10; myQ[nt * 2 + 1] = v01 * v01 + v11 * v11;
    }

    if (st_s) {
        #pragma unroll
        for (int i = 0; i < 8; i++) {
            #pragma unroll
            for (int o = 4; o <= 16; o <<= 1) {
                myS[i] += __shfl_xor_sync(0xffffffffu, myS[i], o);
                myQ[i] += __shfl_xor_sync(0xffffffffu, myQ[i], o);
            }
        }
        if (tg == 0) {
            #pragma unroll
            for (int nt = 0; nt < 4; nt++) {
                Ssum[w][nt * 8 + 2 * tq] = myS[nt * 2];
                Ssum[w][nt * 8 + 2 * tq + 1] = myS[nt * 2 + 1];
                Ssq[w][nt * 8 + 2 * tq] = myQ[nt * 2];
                Ssq[w][nt * 8 + 2 * tq + 1] = myQ[nt * 2 + 1];
            }
        }
        __syncthreads();
        if (tid < 32) {
            float a = Ssum[0][tid] + Ssum[1][tid] + Ssum[2][tid] + Ssum[3][tid];
            float b = Ssq[0][tid] + Ssq[1][tid] + Ssq[2][tid] + Ssq[3][tid];
            atomicAdd(&st_s[col0 + tid], a);
            atomicAdd(&st_s2[col0 + tid], b);
        }
    }
}

// ---------------- mma.sync flash attention (cp.async double-buffered, half-tiles) ----------------
#define QSCALE 0.2944858445807166f
#define NTILES ((NN / SPLITS) / 64)

__global__ __launch_bounds__(128, 6) void flash_mma(const float* __restrict__ qkv,
                                                    const unsigned* __restrict__ kt,
                                                    const unsigned short* __restrict__ vh,
                                                    float* __restrict__ po,
                                                    float* __restrict__ pl) {
    __shared__ __align__(16) unsigned KtU[2][24 * 72];
    __shared__ __align__(16) unsigned short Vh[2][24 * 72];
    const int h   = blockIdx.y;
    const int q0  = blockIdx.x * 128;
    const int sp  = blockIdx.z;
    const int tid = threadIdx.x;
    const int w   = tid >> 5;
    const int lane = tid & 31;
    const int tg = lane >> 2, tq = lane & 3;

    const unsigned* ktb0 = kt + (size_t)h * DH * NN + sp * (NN / SPLITS);
    const unsigned short* vhb0 = vh + (size_t)h * DH * NN + sp * (NN / SPLITS);

    auto stage = [&](int t, int buf) {
        const unsigned* ktb = ktb0 + t * 64;
        const unsigned short* vhb = vhb0 + t * 64;
        unsigned kbase = (unsigned)__cvta_generic_to_shared(&KtU[buf][0]);
        unsigned vbase = (unsigned)__cvta_generic_to_shared(&Vh[buf][0]);
        #pragma unroll
        for (int ii = 0; ii < 3; ii++) {              // K ops 0..383
            int idx = tid + ii * 128;
            int row = idx >> 4, q = idx & 15;
            cp16(kbase + (row * 72 + q * 4) * 4, ktb + (size_t)row * NN + q * 4);
        }
        {                                             // V ops 0..127
            int row = tid >> 3, q = tid & 7;
            cp16(vbase + (row * 72 + q * 8) * 2, vhb + (size_t)row * NN + q * 8);
        }
        if (tid < 64) {                               // V ops 128..191
            int idx = 128 + tid;
            int row = idx >> 3, q = idx & 7;
            cp16(vbase + (row * 72 + q * 8) * 2, vhb + (size_t)row * NN + q * 8);
        }
        asm volatile("cp.async.commit_group;" ::: "memory");
    };

    unsigned QA[2][3][4];
    #pragma unroll
    for (int mi = 0; mi < 2; mi++) {
        const float* qp0 = qkv + (size_t)(q0 + 32 * w + 16 * mi + tg) * (3 * CC) + h * DH;
        const float* qp1 = qp0 + (size_t)8 * (3 * CC);
        #pragma unroll
        for (int kc = 0; kc < 3; kc++) {
            QA[mi][kc][0] = f2tf32(qp0[kc * 8 + tq] * QSCALE);
            QA[mi][kc][1] = f2tf32(qp1[kc * 8 + tq] * QSCALE);
            QA[mi][kc][2] = f2tf32(qp0[kc * 8 + tq + 4] * QSCALE);
            QA[mi][kc][3] = f2tf32(qp1[kc * 8 + tq + 4] * QSCALE);
        }
    }

    float OC[2][3][4];
    #pragma unroll
    for (int mi = 0; mi < 2; mi++)
        #pragma unroll
        for (int n = 0; n < 3; n++)
            #pragma unroll
            for (int r = 0; r < 4; r++) OC[mi][n][r] = 0.f;
    float lacc[2][2] = {{0.f, 0.f}, {0.f, 0.f}};

    stage(0, 0);

    for (int t = 0; t < NTILES; t++) {
        const int buf = t & 1;
        if (t + 1 < NTILES) {
            stage(t + 1, buf ^ 1);
            asm volatile("cp.async.wait_group 1;" ::: "memory");
        } else {
            asm volatile("cp.async.wait_group 0;" ::: "memory");
        }
        __syncthreads();

        #pragma unroll
        for (int kh = 0; kh < 2; kh++) {            // two 32-key halves
            float SC[2][4][4];
            #pragma unroll
            for (int mi = 0; mi < 2; mi++)
                #pragma unroll
                for (int nt = 0; nt < 4; nt++)
                    #pragma unroll
                    for (int r = 0; r < 4; r++) SC[mi][nt][r] = 0.f;

            #pragma unroll
            for (int nt = 0; nt < 4; nt++) {
                const int nc = kh * 32 + nt * 8 + tg;
                unsigned bB[3][2];
                #pragma unroll
                for (int kc = 0; kc < 3; kc++) {
                    bB[kc][0] = KtU[buf][(kc * 8 + tq) * 72 + nc];
                    bB[kc][1] = KtU[buf][(kc * 8 + tq + 4) * 72 + nc];
                }
                #pragma unroll
                for (int kc = 0; kc < 3; kc++) {
                    mma_tf32(SC[0][nt], QA[0][kc], bB[kc]);
                    mma_tf32(SC[1][nt], QA[1][kc], bB[kc]);
                }
            }

            #pragma unroll
            for (int mi = 0; mi < 2; mi++)
                #pragma unroll
                for (int nt = 0; nt < 4; nt++)
                    #pragma unroll
                    for (int r = 0; r < 4; r++) {
                        float e;
                        asm("ex2.approx.ftz.f32 %0, %1;" : "=f"(e) : "f"(SC[mi][nt][r]));
                        SC[mi][nt][r] = e;
                        lacc[mi][r >> 1] += e;
                    }

            unsigned PA[2][2][4];
            #pragma unroll
            for (int mi = 0; mi < 2; mi++)
                #pragma unroll
                for (int kc4 = 0; kc4 < 2; kc4++) {
                    PA[mi][kc4][0] = pkbf(SC[mi][2 * kc4][0],     SC[mi][2 * kc4][1]);
                    PA[mi][kc4][1] = pkbf(SC[mi][2 * kc4][2],     SC[mi][2 * kc4][3]);
                    PA[mi][kc4][2] = pkbf(SC[mi][2 * kc4 + 1][0], SC[mi][2 * kc4 + 1][1]);
                    PA[mi][kc4][3] = pkbf(SC[mi][2 * kc4 + 1][2], SC[mi][2 * kc4 + 1][3]);
                }

            #pragma unroll
            for (int kc4 = 0; kc4 < 2; kc4++) {
                #pragma unroll
                for (int n = 0; n < 3; n++) {
                    int drow = n * 8 + tg;
                    int col = kh * 32 + kc4 * 16 + 2 * tq;
                    unsigned bh[2];
                    bh[0] = *(const unsigned*)&Vh[buf][drow * 72 + col];
                    bh[1] = *(const unsigned*)&Vh[buf][drow * 72 + col + 8];
                    mma_bf16(OC[0][n], PA[0][kc4], bh);
                    mma_bf16(OC[1][n], PA[1][kc4], bh);
                }
            }
        }
        __syncthreads();
    }

    #pragma unroll
    for (int mi = 0; mi < 2; mi++)
        #pragma unroll
        for (int hi = 0; hi < 2; hi++) {
            float v = lacc[mi][hi];
            v += __shfl_xor_sync(0xffffffffu, v, 1);
            v += __shfl_xor_sync(0xffffffffu, v, 2);
            lacc[mi][hi] = v;
        }

    const int base = (sp * NHEADS + h) * NN;
    #pragma unroll
    for (int mi = 0; mi < 2; mi++) {
        int r0 = q0 + 32 * w + 16 * mi + tg;
        int r1 = r0 + 8;
        if (tq == 0) {
            pl[base + r0] = lacc[mi][0];
            pl[base + r1] = lacc[mi][1];
        }
        #pragma unroll
        for (int n = 0; n < 3; n++) {
            float2 v0 = make_float2(OC[mi][n][0], OC[mi][n][1]);
            float2 v1 = make_float2(OC[mi][n][2], OC[mi][n][3]);
            *(float2*)(po + ((size_t)(base + r0)) * DH + n * 8 + 2 * tq) = v0;
            *(float2*)(po + ((size_t)(base + r1)) * DH + n * 8 + 2 * tq) = v1;
        }
    }
}

__global__ void flash_combine(const float* __restrict__ po, const float* __restrict__ pl,
                              float* __restrict__ outp) {
    int t = blockIdx.x * blockDim.x + threadIdx.x;
    if (t >= NN * NHEADS) return;
    int q = t & (NN - 1);
    int h = t >> 12;
    float L = 0.f;
    #pragma unroll
    for (int s = 0; s < SPLITS; s++) L += pl[(s * NHEADS + h) * NN + q];
    float inv = 1.f / L;
    float* op = outp + (size_t)q * CC + h * DH;
    #pragma unroll
    for (int d = 0; d < DH; d += 4) {
        float4 acc = make_float4(0.f, 0.f, 0.f, 0.f);
        #pragma unroll
        for (int s = 0; s < SPLITS; s++) {
            const float4 v = *(const float4*)(po + ((size_t)(s * NHEADS + h) * NN + q) * DH + d);
            acc.x += v.x; acc.y += v.y; acc.z += v.z; acc.w += v.w;
        }
        acc.x *= inv; acc.y *= inv; acc.z *= inv; acc.w *= inv;
        *(float4*)(op + d) = acc;
    }
}

// ---------------- BN elementwise ----------------
__global__ void bn2_add(const float* __restrict__ p1, const float* __restrict__ p2,
                        const float* __restrict__ st,
                        const float* __restrict__ g1, const float* __restrict__ b1,
                        const float* __restrict__ g2, const float* __restrict__ b2,
                        float* __restrict__ out) {
    int i = blockIdx.x * blockDim.x + threadIdx.x;
    if (i >= NN * CC) return;
    int c = i % CC;
    const float invn = 1.f / NN;
    float m1 = st[c] * invn;
    float v1 = st[CC + c] * invn - m1 * m1;
    float m2 = st[2 * CC + c] * invn;
    float v2 = st[3 * CC + c] * invn - m2 * m2;
    float o = (p1[i] - m1) * rsqrtf(v1 + 1e-5f) * g1[c] + b1[c]
            + (p2[i] - m2) * rsqrtf(v2 + 1e-5f) * g2[c] + b2[c];
    out[i] = o;
}

__global__ void bn_apply(const float* __restrict__ p, const float* __restrict__ s,
                         const float* __restrict__ s2, const float* __restrict__ g,
                         const float* __restrict__ b, float* __restrict__ o) {
    int i = blockIdx.x * blockDim.x + threadIdx.x;
    if (i >= NN * CC) return;
    int c = i % CC;
    const float invn = 1.f / NN;
    float m = s[c] * invn;
    float v = s2[c] * invn - m * m;
    o[i] = (p[i] - m) * rsqrtf(v + 1e-5f) * g[c] + b[c];
}

// ---------------- final per-row LayerNorm ----------------
__global__ void out_ln(const float* __restrict__ y, const float* __restrict__ g,
                       const float* __restrict__ b, float* __restrict__ out) {
    int lane = threadIdx.x & 31;
    int warp = threadIdx.x >> 5;
    int row  = blockIdx.x * 4 + warp;
    const float* yr = y + (size_t)row * CC;
    float v0 = yr[lane], v1 = yr[lane + 32], v2 = yr[lane + 64];
    float s = v0 + v1 + v2;
    #pragma unroll
    for (int o = 16; o; o >>= 1) s += __shfl_xor_sync(0xffffffffu, s, o);
    float mean = s * (1.f / 96.f);
    float d0 = v0 - mean, d1 = v1 - mean, d2 = v2 - mean;
    float qv = d0 * d0 + d1 * d1 + d2 * d2;
    #pragma unroll
    for (int o = 16; o; o >>= 1) qv += __shfl_xor_sync(0xffffffffu, qv, o);
    float inv = rsqrtf(qv * (1.f / 96.f) + 1e-5f);
    float* orow = out + (size_t)row * CC;
    orow[lane]      = d0 * inv * g[lane]      + b[lane];
    orow[lane + 32] = d1 * inv * g[lane + 32] + b[lane + 32];
    orow[lane + 64] = d2 * inv * g[lane + 64] + b[lane + 64];
}

// ---------------- launch ----------------
extern "C" void kernel_launch(void* const* d_in, const int* in_sizes, int n_in,
                              void* d_out, int out_size) {
    const float*     x    = (const float*)d_in[0];
    const void*      ei   = d_in[1];
    const void*      ea   = d_in[2];
    const float*     w_in = (const float*)d_in[3];
    const float*     b_in = (const float*)d_in[4];
    const float*     emb  = (const float*)d_in[5];
    const float*     gw1  = (const float*)d_in[6];
    const float*     gb1  = (const float*)d_in[7];
    const float*     gw2  = (const float*)d_in[8];
    const float*     gb2  = (const float*)d_in[9];
    const float*     wqkv = (const float*)d_in[10];
    const float*     bqkv = (const float*)d_in[11];
    const float*     wo   = (const float*)d_in[12];
    const float*     bo   = (const float*)d_in[13];
    const float*     bng  = (const float*)d_in[14];
    const float*     bnb  = (const float*)d_in[15];
    const float*     fw1  = (const float*)d_in[16];
    const float*     fb1  = (const float*)d_in[17];
    const float*     fw2  = (const float*)d_in[18];
    const float*     fb2  = (const float*)d_in[19];
    const float*     w_o  = (const float*)d_in[20];
    const float*     b_o  = (const float*)d_in[21];
    const float*     lng  = (const float*)d_in[22];
    const float*     lnb  = (const float*)d_in[23];
    float* out = (float*)d_out;

    float *h_, *agg_, *t1_, *pre1_, *qkv_, *attno_, *pre2_, *outb_, *t2_, *pre3_, *y_, *stA_;
    float *po_, *pl_;
    unsigned* kt_;
    unsigned short* vh_;
    cudaGetSymbolAddress((void**)&h_,    g_h);
    cudaGetSymbolAddress((void**)&agg_,  g_agg);
    cudaGetSymbolAddress((void**)&t1_,   g_t1);
    cudaGetSymbolAddress((void**)&pre1_, g_pre1);
    cudaGetSymbolAddress((void**)&qkv_,  g_qkv);
    cudaGetSymbolAddress((void**)&attno_,g_attno);
    cudaGetSymbolAddress((void**)&pre2_, g_pre2);
    cudaGetSymbolAddress((void**)&outb_, g_outb);
    cudaGetSymbolAddress((void**)&t2_,   g_t2);
    cudaGetSymbolAddress((void**)&pre3_, g_pre3);
    cudaGetSymbolAddress((void**)&y_,    g_y);
    cudaGetSymbolAddress((void**)&stA_,  g_stats);
    cudaGetSymbolAddress((void**)&po_,   g_po);
    cudaGetSymbolAddress((void**)&pl_,   g_pl);
    cudaGetSymbolAddress((void**)&kt_,   g_kt);
    cudaGetSymbolAddress((void**)&vh_,   g_vh);

    cudaStream_t s1;
    cudaStreamCreateWithFlags(&s1, cudaStreamNonBlocking);
    cudaEvent_t evF[2], evJ[2];
    for (int i = 0; i < 2; i++) {
        cudaEventCreateWithFlags(&evF[i], cudaEventDisableTiming);
        cudaEventCreateWithFlags(&evJ[i], cudaEventDisableTiming);
    }

    auto gemm = [&](const float* A, const float* A2, const float* W, const float* bias,
                    const float* res, float* Cp, int M, int Nc, int K, int relu,
                    float* ss, float* ss2, cudaStream_t st,
                    unsigned* kto = nullptr, unsigned short* vho = nullptr) {
        dim3 grid(Nc / 32, M / 64);
        tgemm<<<grid, 128, 0, st>>>(A, A2, W, bias, res, Cp, M, Nc, K, relu, ss, ss2, kto, vho);
    };

    const int NCEL = NN * CC;

    prep<<<16, 256>>>((const unsigned*)ei, (const unsigned*)ea);
    gemm(x, nullptr, w_in, b_in, nullptr, h_, NN, CC, 64, 0, nullptr, nullptr, 0);

    for (int i = 0; i < 2; i++) {
        float* st_ = stA_ + (size_t)i * 6 * CC;

        cudaEventRecord(evF[i], 0);

        // --- main stream: attention branch ---
        gemm(h_, nullptr, wqkv + (size_t)i * CC * 3 * CC, bqkv + (size_t)i * 3 * CC,
             nullptr, qkv_, NN, 3 * CC, CC, 0, nullptr, nullptr, 0, kt_, vh_);
        flash_mma<<<dim3(NN / 128, NHEADS, SPLITS), 128>>>(qkv_, kt_, vh_, po_, pl_);
        flash_combine<<<(NN * NHEADS + 255) / 256, 256>>>(po_, pl_, attno_);
        gemm(attno_, nullptr, wo + (size_t)i * CC * CC, bo + (size_t)i * CC,
             h_, pre2_, NN, CC, CC, 0, st_ + 2 * CC, st_ + 3 * CC, 0);

        // --- side stream: CSR build (layer 0) + GINE branch ---
        cudaStreamWaitEvent(s1, evF[i], 0);
        if (i == 0) {
            decode_idx<<<(EE + 255) / 256, 256, 0, s1>>>(ei, ea);
            csr_scan<<<1, 1024, 0, s1>>>();
            csr_fill<<<(EE + 255) / 256, 256, 0, s1>>>();
        }
        gine_agg<<<NN / 8, 256, 0, s1>>>(h_, emb, agg_);
        gemm(agg_, h_, gw1, gb1, nullptr, t1_, NN, CC, CC, 1, nullptr, nullptr, s1);
        gemm(t1_, nullptr, gw2, gb2, h_, pre1_, NN, CC, CC, 0, st_ + 0, st_ + CC, s1);
        cudaEventRecord(evJ[i], s1);

        cudaStreamWaitEvent(0, evJ[i], 0);

        // --- merge + FFN (main stream) ---
        bn2_add<<<(NCEL + 255) / 256, 256>>>(pre1_, pre2_, st_,
                                             bng + (size_t)i * 3 * CC, bnb + (size_t)i * 3 * CC,
                                             bng + (size_t)i * 3 * CC + CC, bnb + (size_t)i * 3 * CC + CC,
                                             outb_);
        gemm(outb_, nullptr, fw1 + (size_t)i * CC * 2 * CC, fb1 + (size_t)i * 2 * CC,
             nullptr, t2_, NN, 2 * CC, CC, 1, nullptr, nullptr, 0);
        gemm(t2_, nullptr, fw2 + (size_t)i * 2 * CC * CC, fb2 + (size_t)i * CC,
             outb_, pre3_, NN, CC, 2 * CC, 0, st_ + 4 * CC, st_ + 5 * CC, 0);
        bn_apply<<<(NCEL + 255) / 256, 256>>>(pre3_, st_ + 4 * CC, st_ + 5 * CC,
                                              bng + (size_t)i * 3 * CC + 2 * CC,
                                              bnb + (size_t)i * 3 * CC + 2 * CC, h_);
    }

    gemm(h_, nullptr, w_o, b_o, nullptr, y_, NN, CC, CC, 0, nullptr, nullptr, 0);
    out_ln<<<NN / 4, 128>>>(y_, lng, lnb, out);
}